// round 3
// baseline (speedup 1.0000x reference)
#include <cuda_runtime.h>
#include <math.h>

// Problem constants
#define BS    4
#define CC    64
#define HH    128
#define WW    128
#define HW    (HH * WW)        // 16384 pixels per image
#define NPIX  (BS * HW)        // 65536 pixels total
#define NTOT  (NPIX * CC)      // 4194304 field elements
#define O2    128              // hidden = 2C
#define DT    0.1f
#define THRESH 0.01
#define NSTEPS 50

// Step-kernel geometry
#define BLOCKS   1024
#define THREADS  256
#define WARPS    8
#define PPW      (NPIX / (BLOCKS * WARPS))   // 8 pixels per warp

// Padded shared layouts (conflict-free vector LDS)
#define W1_PITCH 132   // floats per c-row; row byte stride 528 (16B aligned)
#define W2_PITCH 66    // floats per o-row; row byte stride 264 (8B aligned)
#define SMEM_FLOATS (CC * W1_PITCH + O2 * W2_PITCH + WARPS * CC + WARPS * O2)
#define SMEM_BYTES  (SMEM_FLOATS * 4 + WARPS * 8)   // + double[8] reduction

// Persistent device state (no allocations allowed)
__device__ float  g_f0[NTOT];
__device__ float  g_f1[NTOT];
__device__ int    g_done;
__device__ int    g_parity;
__device__ int    g_steps;
__device__ double g_sum;

__global__ void reset_kernel() {
    g_done = 0; g_parity = 0; g_steps = 0; g_sum = 0.0;
}

// NCHW -> NHWC (internal layout), tiled transpose of [C, HW] per image
__global__ void nchw_to_nhwc(const float* __restrict__ in) {
    __shared__ float tile[32][33];
    int b  = blockIdx.z;
    int p0 = blockIdx.x * 32;
    int c0 = blockIdx.y * 32;
    const float* src = in   + (size_t)b * CC * HW;
    float*       dst = g_f0 + (size_t)b * HW * CC;
    for (int i = threadIdx.y; i < 32; i += 8)
        tile[i][threadIdx.x] = src[(size_t)(c0 + i) * HW + p0 + threadIdx.x];
    __syncthreads();
    for (int i = threadIdx.y; i < 32; i += 8)
        dst[(size_t)(p0 + i) * CC + c0 + threadIdx.x] = tile[threadIdx.x][i];
}

// NHWC (current parity buffer) -> NCHW into d_out
__global__ void nhwc_to_nchw(float* __restrict__ out) {
    __shared__ float tile[32][33];
    const float* srcbuf = g_parity ? g_f1 : g_f0;
    int b  = blockIdx.z;
    int p0 = blockIdx.x * 32;
    int c0 = blockIdx.y * 32;
    const float* src = srcbuf + (size_t)b * HW * CC;
    float*       dst = out    + (size_t)b * CC * HW;
    for (int i = threadIdx.y; i < 32; i += 8)
        tile[i][threadIdx.x] = src[(size_t)(p0 + i) * CC + c0 + threadIdx.x];
    __syncthreads();
    for (int i = threadIdx.y; i < 32; i += 8)
        dst[(size_t)(c0 + i) * HW + p0 + threadIdx.x] = tile[threadIdx.x][i];
}

__global__ void write_steps(float* out, int out_size) {
    for (int i = NTOT; i < out_size; i++) out[i] = (float)g_steps;
}

__global__ void finalize_kernel() {
    if (!g_done) {
        double change = g_sum * (1.0 / (double)NTOT);
        g_steps += 1;
        g_parity ^= 1;
        if (change < THRESH) g_done = 1;
    }
    g_sum = 0.0;
}

__device__ __forceinline__ float gelu_exact(float v) {
    // approximate=False gelu: 0.5*x*(1+erf(x/sqrt(2)))
    return 0.5f * v * (1.0f + erff(v * 0.70710678118654752440f));
}

// Fused step: depthwise 3x3 conv + (64 -> gelu 128 -> 64) MLP + Euler update
// One warp per pixel; weights staged in SMEM with conflict-free packed layouts.
__global__ __launch_bounds__(THREADS)
void step_kernel(const float* __restrict__ dw, const float* __restrict__ db,
                 const float* __restrict__ w1, const float* __restrict__ b1,
                 const float* __restrict__ w2, const float* __restrict__ b2,
                 const float* __restrict__ dcoeff)
{
    if (g_done) return;   // converged: frozen field, no-op launch

    extern __shared__ float smem[];
    float*  sW1  = smem;                          // [64][132]  w1 packed [c][o]
    float*  sW2  = sW1 + CC * W1_PITCH;           // [128][66]  w2 packed pairs
    float*  sF   = sW2 + O2 * W2_PITCH;           // [8][64]    per-warp f vec
    float*  sH   = sF + WARPS * CC;               // [8][128]   per-warp hidden
    double* sRed = (double*)(sH + WARPS * O2);    // [8]

    const float* src = g_parity ? g_f1 : g_f0;
    float*       dst = g_parity ? g_f0 : g_f1;

    int tid = threadIdx.x;

    // Stage W1: coalesced read w1[o*64+c], scatter to sW1[c*132 + o]
    for (int i = tid; i < CC * O2; i += THREADS) {
        int o = i >> 6, c = i & 63;
        sW1[c * W1_PITCH + o] = w1[i];
    }
    // Stage W2: coalesced read w2[c*128+o], pack pairs (c, c+32) per o-row
    for (int i = tid; i < CC * O2; i += THREADS) {
        int c = i >> 7, o = i & 127;
        sW2[o * W2_PITCH + ((c & 31) << 1) + (c >> 5)] = w2[i];
    }
    __syncthreads();

    int lane = tid & 31, wid = tid >> 5;
    float* sFw = sF + wid * CC;
    float* sHw = sH + wid * O2;

    // Per-lane constants (lane owns channels {lane, lane+32})
    float dwr0[9], dwr1[9];
    #pragma unroll
    for (int k = 0; k < 9; k++) {
        dwr0[k] = dw[lane * 9 + k];
        dwr1[k] = dw[(lane + 32) * 9 + k];
    }
    float  dbr0 = db[lane], dbr1 = db[lane + 32];
    float4 b1v  = ((const float4*)b1)[lane];          // o = 4*lane .. 4*lane+3
    float  b2r0 = b2[lane], b2r1 = b2[lane + 32];
    float  dc   = dcoeff[0];

    float asum = 0.0f;
    int pbase = (blockIdx.x * WARPS + wid) * PPW;

    for (int pi = 0; pi < PPW; pi++) {
        int p = pbase + pi;
        int b = p >> 14;
        int y = (p >> 7) & 127;
        int x = p & 127;
        const float* base = src + (size_t)b * (HW * CC);
        int cidx = (y * WW + x) << 6;

        float fc0 = base[cidx + lane];
        float fc1 = base[cidx + 32 + lane];

        // Depthwise 3x3 conv (cross-correlation, SAME zero-pad)
        float d0 = dbr0, d1 = dbr1;
        #pragma unroll
        for (int k = 0; k < 9; k++) {
            float v0, v1;
            if (k == 4) { v0 = fc0; v1 = fc1; }
            else {
                int yy = y + k / 3 - 1;
                int xx = x + (k % 3) - 1;
                if ((unsigned)yy < HH && (unsigned)xx < WW) {
                    int ni = (yy * WW + xx) << 6;
                    v0 = base[ni + lane];
                    v1 = base[ni + 32 + lane];
                } else { v0 = 0.0f; v1 = 0.0f; }
            }
            d0 = fmaf(dwr0[k], v0, d0);
            d1 = fmaf(dwr1[k], v1, d1);
        }

        // Share f vector within warp
        sFw[lane]      = fc0;
        sFw[lane + 32] = fc1;
        __syncwarp();

        // GEMM1: h = gelu(W1 @ f + b1); lane computes o = 4*lane..4*lane+3
        float a0 = b1v.x, a1 = b1v.y, a2 = b1v.z, a3 = b1v.w;
        #pragma unroll 16
        for (int c = 0; c < CC; c++) {
            float  fcc = sFw[c];                                  // broadcast
            float4 w = *(const float4*)(sW1 + c * W1_PITCH + (lane << 2));
            a0 = fmaf(w.x, fcc, a0);
            a1 = fmaf(w.y, fcc, a1);
            a2 = fmaf(w.z, fcc, a2);
            a3 = fmaf(w.w, fcc, a3);
        }
        a0 = gelu_exact(a0); a1 = gelu_exact(a1);
        a2 = gelu_exact(a2); a3 = gelu_exact(a3);
        *(float4*)(sHw + (lane << 2)) = make_float4(a0, a1, a2, a3);
        __syncwarp();

        // GEMM2: react = W2 @ h + b2; lane computes channels {lane, lane+32}
        float r0 = b2r0, r1 = b2r1;
        #pragma unroll 16
        for (int o = 0; o < O2; o++) {
            float  ho = sHw[o];                                   // broadcast
            float2 w = *(const float2*)(sW2 + o * W2_PITCH + (lane << 1));
            r0 = fmaf(w.x, ho, r0);
            r1 = fmaf(w.y, ho, r1);
        }

        // Euler update + |delta| accumulation (post-rounding, matching ref)
        float n0 = fc0 + DT * fmaf(dc, d0, r0);
        float n1 = fc1 + DT * fmaf(dc, d1, r1);
        float* dbase = dst + (size_t)b * (HW * CC);
        dbase[cidx + lane]      = n0;
        dbase[cidx + 32 + lane] = n1;
        asum += fabsf(n0 - fc0) + fabsf(n1 - fc1);
        __syncwarp();   // protect sFw/sHw before next pixel rewrites them
    }

    // Block reduction of |delta| sum -> double atomic
    #pragma unroll
    for (int off = 16; off; off >>= 1)
        asum += __shfl_xor_sync(0xffffffffu, asum, off);
    if (lane == 0) sRed[wid] = (double)asum;
    __syncthreads();
    if (tid == 0) {
        double s = 0.0;
        #pragma unroll
        for (int i = 0; i < WARPS; i++) s += sRed[i];
        atomicAdd(&g_sum, s);
    }
}

extern "C" void kernel_launch(void* const* d_in, const int* in_sizes, int n_in,
                              void* d_out, int out_size) {
    const float* field  = (const float*)d_in[0];
    const float* dw     = (const float*)d_in[1];
    const float* db     = (const float*)d_in[2];
    const float* w1     = (const float*)d_in[3];
    const float* b1     = (const float*)d_in[4];
    const float* w2     = (const float*)d_in[5];
    const float* b2     = (const float*)d_in[6];
    const float* dcoeff = (const float*)d_in[7];
    // d_in[8] = max_steps (always 50 per setup_inputs)

    cudaFuncSetAttribute(step_kernel,
                         cudaFuncAttributeMaxDynamicSharedMemorySize, SMEM_BYTES);

    reset_kernel<<<1, 1>>>();

    dim3 tb(32, 8), tg(HW / 32, CC / 32, BS);
    nchw_to_nhwc<<<tg, tb>>>(field);

    for (int s = 0; s < NSTEPS; s++) {
        step_kernel<<<BLOCKS, THREADS, SMEM_BYTES>>>(dw, db, w1, b1, w2, b2, dcoeff);
        finalize_kernel<<<1, 1>>>();
    }

    nhwc_to_nchw<<<tg, tb>>>((float*)d_out);
    write_steps<<<1, 1>>>((float*)d_out, out_size);
}

// round 8
// speedup vs baseline: 2.4068x; 2.4068x over previous
#include <cuda_runtime.h>
#include <math.h>

// Problem constants
#define BS    4
#define CC    64
#define HH    128
#define WW    128
#define HW    (HH * WW)
#define NPIX  (BS * HW)        // 65536 pixels
#define NTOT  (NPIX * CC)      // 4194304 field elements
#define O2    128
#define DT    0.1f
#define THRESH 0.01
#define NSTEPS 50

// Step-kernel geometry: one warp processes 8 consecutive pixels as a batch
#define BLOCKS   1024
#define THREADS  256
#define WARPS    8
#define PIXB     8            // pixels per warp batch (one batch per warp per step)

// SMEM layouts
#define W1P 132               // w1 row pitch (floats): [c][o], LDS.128 at 4*lane
#define W2P 66                // w2 row pitch: [r][2*lane] channel pairs, rows o-permuted
#define BP  10                // per-warp f/h staging pitch (2-way conflict worst case)
#define BUFW (O2 * BP)        // 1280 floats per warp (f rows 0..63 alias h rows 0..127)
#define SMEM_FLOATS (CC * W1P + O2 * W2P + WARPS * BUFW)
#define SMEM_BYTES  (SMEM_FLOATS * 4 + WARPS * 8)

// Persistent device state
__device__ float    g_f0[NTOT];
__device__ float    g_f1[NTOT];
__device__ int      g_done;
__device__ int      g_parity;
__device__ int      g_steps;
__device__ double   g_sum;
__device__ unsigned g_count;

__global__ void reset_kernel() {
    g_done = 0; g_parity = 0; g_steps = 0; g_sum = 0.0; g_count = 0u;
}

// NCHW -> NHWC
__global__ void nchw_to_nhwc(const float* __restrict__ in) {
    __shared__ float tile[32][33];
    int b  = blockIdx.z;
    int p0 = blockIdx.x * 32;
    int c0 = blockIdx.y * 32;
    const float* src = in   + (size_t)b * CC * HW;
    float*       dst = g_f0 + (size_t)b * HW * CC;
    for (int i = threadIdx.y; i < 32; i += 8)
        tile[i][threadIdx.x] = src[(size_t)(c0 + i) * HW + p0 + threadIdx.x];
    __syncthreads();
    for (int i = threadIdx.y; i < 32; i += 8)
        dst[(size_t)(p0 + i) * CC + c0 + threadIdx.x] = tile[threadIdx.x][i];
}

// NHWC (current parity) -> NCHW into d_out
__global__ void nhwc_to_nchw(float* __restrict__ out) {
    __shared__ float tile[32][33];
    const float* srcbuf = g_parity ? g_f1 : g_f0;
    int b  = blockIdx.z;
    int p0 = blockIdx.x * 32;
    int c0 = blockIdx.y * 32;
    const float* src = srcbuf + (size_t)b * HW * CC;
    float*       dst = out    + (size_t)b * CC * HW;
    for (int i = threadIdx.y; i < 32; i += 8)
        tile[i][threadIdx.x] = src[(size_t)(p0 + i) * CC + c0 + threadIdx.x];
    __syncthreads();
    for (int i = threadIdx.y; i < 32; i += 8)
        dst[(size_t)(c0 + i) * HW + p0 + threadIdx.x] = tile[threadIdx.x][i];
}

__global__ void write_steps(float* out, int out_size) {
    for (int i = NTOT; i < out_size; i++) out[i] = (float)g_steps;
}

__device__ __forceinline__ float gelu_exact(float v) {
    return 0.5f * v * (1.0f + erff(v * 0.70710678118654752440f));
}

// ---- packed f32x2 helpers (sm_103a FFMA2) ----
__device__ __forceinline__ unsigned long long dup2(float v) {
    unsigned long long r;
    asm("mov.b64 %0, {%1, %1};" : "=l"(r) : "f"(v));
    return r;
}
__device__ __forceinline__ void ffma2(unsigned long long& acc,
                                      unsigned long long a, unsigned long long b) {
    asm("fma.rn.f32x2 %0, %1, %2, %0;" : "+l"(acc) : "l"(a), "l"(b));
}
__device__ __forceinline__ void unpack2(unsigned long long v, float& lo, float& hi) {
    asm("mov.b64 {%0, %1}, %2;" : "=f"(lo), "=f"(hi) : "l"(v));
}

// Fused step: 8-pixel-per-warp batch; weights read from SMEM once per batch.
__global__ __launch_bounds__(THREADS, 2)
void step_kernel(const float* __restrict__ dw, const float* __restrict__ db,
                 const float* __restrict__ w1, const float* __restrict__ b1,
                 const float* __restrict__ w2, const float* __restrict__ b2,
                 const float* __restrict__ dcoeff)
{
    if (g_done) return;

    extern __shared__ float smem[];
    float*  sW1  = smem;                          // [64][132]
    float*  sW2  = sW1 + CC * W1P;                // [128][66], rows r=(o&3)*32+(o>>2)
    float*  sBuf = sW2 + O2 * W2P;                // [8 warps][1280]
    double* sRed = (double*)(sBuf + WARPS * BUFW);

    const float* src = g_parity ? g_f1 : g_f0;
    float*       dst = g_parity ? g_f0 : g_f1;

    int tid = threadIdx.x;

    // Stage W1: w1[o*64+c] -> sW1[c*132 + o]
    for (int i = tid; i < CC * O2; i += THREADS) {
        int o = i >> 6, c = i & 63;
        sW1[c * W1P + o] = w1[i];
    }
    // Stage W2: w2[c*128+o] -> permuted row r, channel-pair packed
    for (int i = tid; i < CC * O2; i += THREADS) {
        int c = i >> 7, o = i & 127;
        int r = ((o & 3) << 5) + (o >> 2);
        sW2[r * W2P + ((c & 31) << 1) + (c >> 5)] = w2[i];
    }
    __syncthreads();

    int lane = tid & 31, wid = tid >> 5;
    float* sFw = sBuf + wid * BUFW;   // per-warp staging (f rows alias h rows)

    // Per-lane constants: lane owns channels {lane, lane+32}
    float dwr0[9], dwr1[9];
    #pragma unroll
    for (int k = 0; k < 9; k++) {
        dwr0[k] = dw[lane * 9 + k];
        dwr1[k] = dw[(lane + 32) * 9 + k];
    }
    float  dbr0 = db[lane], dbr1 = db[lane + 32];
    float4 b1v  = ((const float4*)b1)[lane];       // o = 4*lane .. 4*lane+3
    float  b2r0 = b2[lane], b2r1 = b2[lane + 32];
    float  dc   = dcoeff[0];

    // ---- Phase A: load f + depthwise conv for 8 consecutive pixels (one row) ----
    int p0 = (blockIdx.x * WARPS + wid) * PIXB;
    int b  = p0 >> 14;
    int y  = (p0 >> 7) & 127;
    int x  = p0 & 127;                              // multiple of 8
    const float* base = src + (size_t)b * (HW * CC);

    float fc0[PIXB], fc1[PIXB], d0[PIXB], d1[PIXB];
    #pragma unroll
    for (int i = 0; i < PIXB; i++) { d0[i] = dbr0; d1[i] = dbr1; }

    #pragma unroll
    for (int r = 0; r < 3; r++) {
        int yy = y + r - 1;
        bool rowok = (unsigned)yy < HH;
        #pragma unroll
        for (int cc = 0; cc < 10; cc++) {
            int xx = x + cc - 1;
            float v0 = 0.0f, v1 = 0.0f;
            if (rowok && (unsigned)xx < WW) {
                int ni = (yy * WW + xx) << 6;
                v0 = base[ni + lane];
                v1 = base[ni + 32 + lane];
            }
            if (r == 1 && cc >= 1 && cc <= 8) { fc0[cc - 1] = v0; fc1[cc - 1] = v1; }
            int plo = cc - 2 < 0 ? 0 : cc - 2;
            int phi = cc > 7 ? 7 : cc;
            #pragma unroll
            for (int pi = plo; pi <= phi; pi++) {
                int k = r * 3 + (cc - pi);
                d0[pi] = fmaf(dwr0[k], v0, d0[pi]);
                d1[pi] = fmaf(dwr1[k], v1, d1[pi]);
            }
        }
    }

    // Stage f: sFt[c][pix], pitch BP; lane writes its two channel rows
    #pragma unroll
    for (int pp = 0; pp < 4; pp++) {
        *(float2*)(sFw + lane * BP + 2 * pp)        = make_float2(fc0[2*pp], fc0[2*pp+1]);
        *(float2*)(sFw + (lane + 32) * BP + 2 * pp) = make_float2(fc1[2*pp], fc1[2*pp+1]);
    }
    __syncwarp();

    // ---- Phase B: GEMM1 h = gelu(W1 @ f + b1), f32x2 over pixel pairs ----
    // acc1[j][pp]: (h[4*lane+j][2pp], h[4*lane+j][2pp+1])
    unsigned long long acc1[4][4];
    #pragma unroll
    for (int j = 0; j < 4; j++) {
        unsigned long long bb = dup2(j == 0 ? b1v.x : j == 1 ? b1v.y : j == 2 ? b1v.z : b1v.w);
        #pragma unroll
        for (int pp = 0; pp < 4; pp++) acc1[j][pp] = bb;
    }
    #pragma unroll 8
    for (int c = 0; c < CC; c++) {
        float4 w = *(const float4*)(sW1 + c * W1P + (lane << 2));
        unsigned long long a0 = dup2(w.x), a1 = dup2(w.y), a2 = dup2(w.z), a3 = dup2(w.w);
        #pragma unroll
        for (int pp = 0; pp < 4; pp++) {
            unsigned long long f2 = *(const unsigned long long*)(sFw + c * BP + 2 * pp);
            ffma2(acc1[0][pp], a0, f2);
            ffma2(acc1[1][pp], a1, f2);
            ffma2(acc1[2][pp], a2, f2);
            ffma2(acc1[3][pp], a3, f2);
        }
    }
    __syncwarp();

    // gelu + stage h at permuted rows r = j*32 + lane (conflict-free: one row per lane)
    #pragma unroll
    for (int j = 0; j < 4; j++) {
        #pragma unroll
        for (int pp = 0; pp < 4; pp++) {
            float lo, hi; unpack2(acc1[j][pp], lo, hi);
            lo = gelu_exact(lo); hi = gelu_exact(hi);
            *(float2*)(sFw + (j * 32 + lane) * BP + 2 * pp) = make_float2(lo, hi);
        }
    }
    __syncwarp();

    // ---- Phase C: GEMM2 react = W2 @ h + b2, f32x2 over pixel pairs ----
    // acc2[ch][pp]: ch 0 -> lane, ch 1 -> lane+32
    unsigned long long acc2[2][4];
    {
        unsigned long long bb0 = dup2(b2r0), bb1 = dup2(b2r1);
        #pragma unroll
        for (int pp = 0; pp < 4; pp++) { acc2[0][pp] = bb0; acc2[1][pp] = bb1; }
    }
    #pragma unroll 8
    for (int r = 0; r < O2; r++) {
        float2 wv = *(const float2*)(sW2 + r * W2P + (lane << 1));
        unsigned long long a0 = dup2(wv.x), a1 = dup2(wv.y);
        #pragma unroll
        for (int pp = 0; pp < 4; pp++) {
            unsigned long long h2 = *(const unsigned long long*)(sFw + r * BP + 2 * pp);
            ffma2(acc2[0][pp], a0, h2);
            ffma2(acc2[1][pp], a1, h2);
        }
    }

    // ---- Phase D: Euler update + |delta| ----
    float asum = 0.0f;
    float* dbase = dst + (size_t)b * (HW * CC);
    #pragma unroll
    for (int pp = 0; pp < 4; pp++) {
        float r0lo, r0hi, r1lo, r1hi;
        unpack2(acc2[0][pp], r0lo, r0hi);
        unpack2(acc2[1][pp], r1lo, r1hi);
        #pragma unroll
        for (int hf = 0; hf < 2; hf++) {
            int   pi = 2 * pp + hf;
            float r0 = hf ? r0hi : r0lo;
            float r1 = hf ? r1hi : r1lo;
            float n0 = fc0[pi] + DT * fmaf(dc, d0[pi], r0);
            float n1 = fc1[pi] + DT * fmaf(dc, d1[pi], r1);
            int ci = ((y * WW) + x + pi) << 6;
            dbase[ci + lane]      = n0;
            dbase[ci + 32 + lane] = n1;
            asum += fabsf(n0 - fc0[pi]) + fabsf(n1 - fc1[pi]);
        }
    }

    // ---- Reduction + fused finalize in last block ----
    #pragma unroll
    for (int off = 16; off; off >>= 1)
        asum += __shfl_xor_sync(0xffffffffu, asum, off);
    if (lane == 0) sRed[wid] = (double)asum;
    __syncthreads();
    if (tid == 0) {
        double s = 0.0;
        #pragma unroll
        for (int i = 0; i < WARPS; i++) s += sRed[i];
        atomicAdd(&g_sum, s);
        __threadfence();
        unsigned t = atomicInc(&g_count, BLOCKS - 1);
        if (t == BLOCKS - 1) {            // last block of this step: finalize
            double change = *((volatile double*)&g_sum) * (1.0 / (double)NTOT);
            g_steps += 1;
            g_parity ^= 1;
            if (change < THRESH) g_done = 1;
            g_sum = 0.0;
        }
    }
}

extern "C" void kernel_launch(void* const* d_in, const int* in_sizes, int n_in,
                              void* d_out, int out_size) {
    const float* field  = (const float*)d_in[0];
    const float* dw     = (const float*)d_in[1];
    const float* db     = (const float*)d_in[2];
    const float* w1     = (const float*)d_in[3];
    const float* b1     = (const float*)d_in[4];
    const float* w2     = (const float*)d_in[5];
    const float* b2     = (const float*)d_in[6];
    const float* dcoeff = (const float*)d_in[7];

    cudaFuncSetAttribute(step_kernel,
                         cudaFuncAttributeMaxDynamicSharedMemorySize, SMEM_BYTES);

    reset_kernel<<<1, 1>>>();

    dim3 tb(32, 8), tg(HW / 32, CC / 32, BS);
    nchw_to_nhwc<<<tg, tb>>>(field);

    for (int s = 0; s < NSTEPS; s++)
        step_kernel<<<BLOCKS, THREADS, SMEM_BYTES>>>(dw, db, w1, b1, w2, b2, dcoeff);

    nhwc_to_nchw<<<tg, tb>>>((float*)d_out);
    write_steps<<<1, 1>>>((float*)d_out, out_size);
}